// round 1
// baseline (speedup 1.0000x reference)
#include <cuda_runtime.h>
#include <cstdint>

#define KV      8
#define GRP     4
#define NH      32
#define BATCH   16
#define HD      128
#define CTX     32768
#define CACHE   32736
#define NQ      64          // GRP*BATCH queries per kv head
#define TC      64          // ctx tile
#define NCH     37          // chunks -> 296 blocks = 2 waves-per-SM exactly
#define NT      (CTX / TC)  // 512 tiles total
#define NTHR    256

// -------- scratch (static device globals; no runtime allocation) --------
__device__ float g_pout[NCH * KV * NQ * HD];   // ~4.85 MB
__device__ float g_pm[NCH * KV * NQ];
__device__ float g_pl[NCH * KV * NQ];

typedef unsigned long long u64;

__device__ __forceinline__ u64 ffma2(u64 a, u64 b, u64 c) {
    u64 d; asm("fma.rn.f32x2 %0, %1, %2, %3;" : "=l"(d) : "l"(a), "l"(b), "l"(c)); return d;
}
__device__ __forceinline__ u64 fmul2(u64 a, u64 b) {
    u64 d; asm("mul.rn.f32x2 %0, %1, %2;" : "=l"(d) : "l"(a), "l"(b)); return d;
}
__device__ __forceinline__ u64 dup2(float x) {
    u64 r; asm("mov.b64 %0, {%1, %2};" : "=l"(r) : "f"(x), "f"(x)); return r;
}
__device__ __forceinline__ float2 unpk(u64 v) {
    float2 f; asm("mov.b64 {%0, %1}, %2;" : "=f"(f.x), "=f"(f.y) : "l"(v)); return f;
}
__device__ __forceinline__ float neg_inf() { return __int_as_float(0xff800000); }

// -------- kernel 0: scaled_keys / scaled_values outputs --------
__global__ void k_scale(const float* __restrict__ keys, const float* __restrict__ values,
                        const float* __restrict__ kq_scale,
                        float* __restrict__ out_sk, float* __restrict__ out_sv) {
    int i = blockIdx.x * blockDim.x + threadIdx.x;
    if (i < KV * BATCH * HD) {
        float s = kq_scale[0];
        out_sk[i] = keys[i] * s;
        out_sv[i] = fmaxf(values[i], -10000.0f);
    }
}

// -------- kernel 1: flash-decode partials over ctx chunks --------
// smem: Qt[HD][NQ] | Ks[HD][TC] (overlaid by Ps[NQ][TC]) | Vs[TC][HD] | m,l,scale[NQ]
#define SMEM_BYTES ((8192 * 3 + 192) * 4)

__global__ void __launch_bounds__(NTHR, 2)
k_attn(const float* __restrict__ q_g, const float* __restrict__ ktc,
       const float* __restrict__ vc, const float* __restrict__ bias,
       const float* __restrict__ sk, const float* __restrict__ sv) {
    extern __shared__ float sm[];
    float* Qt   = sm;            // [d][q]
    float* Ks   = sm + 8192;     // [d][c]
    float* Vs   = sm + 16384;    // [c][d]
    float* m_s  = sm + 24576;
    float* l_s  = sm + 24640;
    float* sc_s = sm + 24704;
    float* Ps   = Ks;            // overlay: [q][c]

    const int ch = blockIdx.x, kv = blockIdx.y;
    const int tid = threadIdx.x;
    const int ty = tid >> 4, tx = tid & 15;
    const int q0 = ty << 2, t4 = tx << 2;

    // load Q transposed: Qt[d][q], q = g*16+b
    const float* qb = q_g + (size_t)kv * (GRP * BATCH * HD);
    #pragma unroll
    for (int r = 0; r < 32; r++) {
        int idx = tid + r * NTHR;          // 0..8191
        int q = idx >> 7, d = idx & 127;
        Qt[d * NQ + q] = qb[idx];
    }
    if (tid < NQ) { m_s[tid] = neg_inf(); l_s[tid] = 0.0f; }

    u64 accO[4][4];
    #pragma unroll
    for (int i = 0; i < 4; i++)
        #pragma unroll
        for (int k = 0; k < 4; k++) accO[i][k] = 0ull;

    const int tb = (ch * NT) / NCH, te = ((ch + 1) * NT) / NCH;
    const float* kbase = ktc + (size_t)kv * HD * CACHE;
    const float* vbase = vc  + (size_t)kv * CACHE * HD;
    const float* skb   = sk  + kv * BATCH * HD;
    const float* svb   = sv  + kv * BATCH * HD;

    for (int t = tb; t < te; t++) {
        const int c0 = t * TC;
        __syncthreads();   // prev GEMM2 done with Vs/Ps

        // --- load K tile (coalesced rows of K^T cache), zero-fill OOB ---
        #pragma unroll
        for (int r = 0; r < 8; r++) {
            int idx = tid + r * NTHR;                 // float4 units, 0..2047
            int d = idx >> 4, cl4 = (idx & 15) << 2;
            int c = c0 + cl4;
            float4 v = (c < CACHE) ? *(const float4*)(kbase + (size_t)d * CACHE + c)
                                   : make_float4(0.f, 0.f, 0.f, 0.f);
            *(float4*)(Ks + d * TC + cl4) = v;
        }
        // --- load V tile ---
        #pragma unroll
        for (int r = 0; r < 8; r++) {
            int idx = tid + r * NTHR;
            int cl = idx >> 5, d4 = (idx & 31) << 2;
            int c = c0 + cl;
            float4 v = (c < CACHE) ? *(const float4*)(vbase + (size_t)c * HD + d4)
                                   : make_float4(0.f, 0.f, 0.f, 0.f);
            *(float4*)(Vs + cl * HD + d4) = v;
        }
        // --- overlay the 16 new tokens (last tile only) ---
        if (c0 + TC > CACHE) {
            int off = CACHE - c0;                      // 32
            for (int idx = tid; idx < BATCH * HD; idx += NTHR) {
                int cn = idx >> 7, d = idx & 127;
                Ks[d * TC + off + cn] = skb[idx];
            }
            for (int idx = tid; idx < BATCH * (HD / 4); idx += NTHR) {
                int cn = idx >> 5, d4 = (idx & 31) << 2;
                *(float4*)(Vs + (off + cn) * HD + d4) = *(const float4*)(svb + cn * HD + d4);
            }
        }
        __syncthreads();

        // --- GEMM1: S[4q][4c] via f32x2 (pairs over c) ---
        u64 accS[4][2];
        #pragma unroll
        for (int i = 0; i < 4; i++) { accS[i][0] = 0ull; accS[i][1] = 0ull; }
        {
            const float* qrow = Qt + q0;
            const float* krow = Ks + t4;
            #pragma unroll 8
            for (int d = 0; d < HD; d++) {
                float4 a = *(const float4*)(qrow + d * NQ);
                ulonglong2 b = *(const ulonglong2*)(krow + d * TC);
                u64 a0 = dup2(a.x), a1 = dup2(a.y), a2 = dup2(a.z), a3 = dup2(a.w);
                accS[0][0] = ffma2(a0, b.x, accS[0][0]); accS[0][1] = ffma2(a0, b.y, accS[0][1]);
                accS[1][0] = ffma2(a1, b.x, accS[1][0]); accS[1][1] = ffma2(a1, b.y, accS[1][1]);
                accS[2][0] = ffma2(a2, b.x, accS[2][0]); accS[2][1] = ffma2(a2, b.y, accS[2][1]);
                accS[3][0] = ffma2(a3, b.x, accS[3][0]); accS[3][1] = ffma2(a3, b.y, accS[3][1]);
            }
        }
        __syncthreads();   // GEMM1 done reading Ks -> safe to overwrite with Ps

        // --- online softmax epilogue ---
        float s[4][4];
        #pragma unroll
        for (int i = 0; i < 4; i++) {
            float2 p0 = unpk(accS[i][0]), p1 = unpk(accS[i][1]);
            s[i][0] = p0.x; s[i][1] = p0.y; s[i][2] = p1.x; s[i][3] = p1.y;
        }
        if (c0 + TC > CACHE) {   // bias is exactly 0 everywhere else; read real input here
            #pragma unroll
            for (int i = 0; i < 4; i++) {
                int b = (q0 + i) & 15;
                #pragma unroll
                for (int j = 0; j < 4; j++) s[i][j] += bias[(size_t)b * CTX + c0 + t4 + j];
            }
        }
        float mold[4], lold[4], mnew[4], scl[4], lsum[4];
        float pr[4][4];
        #pragma unroll
        for (int i = 0; i < 4; i++) {
            int q = q0 + i;
            float mx = fmaxf(fmaxf(s[i][0], s[i][1]), fmaxf(s[i][2], s[i][3]));
            #pragma unroll
            for (int off = 8; off >= 1; off >>= 1)
                mx = fmaxf(mx, __shfl_xor_sync(0xffffffffu, mx, off, 16));
            mold[i] = m_s[q]; lold[i] = l_s[q];
            mnew[i] = fmaxf(mold[i], mx);
            float ls = 0.f;
            #pragma unroll
            for (int j = 0; j < 4; j++) { pr[i][j] = __expf(s[i][j] - mnew[i]); ls += pr[i][j]; }
            #pragma unroll
            for (int off = 8; off >= 1; off >>= 1)
                ls += __shfl_xor_sync(0xffffffffu, ls, off, 16);
            lsum[i] = ls;
            scl[i] = __expf(mold[i] - mnew[i]);    // exp(-inf)=0 on first tile
        }
        __syncwarp();  // all lanes read m_s/l_s before any lane writes
        #pragma unroll
        for (int i = 0; i < 4; i++) {
            int q = q0 + i;
            m_s[q]  = mnew[i];                     // identical value from all 16 lanes
            l_s[q]  = lold[i] * scl[i] + lsum[i];
            sc_s[q] = scl[i];
            *(float4*)(Ps + q * TC + t4) = make_float4(pr[i][0], pr[i][1], pr[i][2], pr[i][3]);
        }
        __syncthreads();

        // --- GEMM2: O[4q][8d] += P * V, f32x2 (pairs over d) ---
        #pragma unroll
        for (int i = 0; i < 4; i++) {
            u64 s2 = dup2(sc_s[q0 + i]);
            #pragma unroll
            for (int k = 0; k < 4; k++) accO[i][k] = fmul2(accO[i][k], s2);
        }
        {
            const float* vcol = Vs + t4;
            const float* prow = Ps + q0 * TC;
            #pragma unroll 4
            for (int c = 0; c < TC; c++) {
                ulonglong2 v01 = *(const ulonglong2*)(vcol + c * HD);
                ulonglong2 v23 = *(const ulonglong2*)(vcol + c * HD + 64);
                #pragma unroll
                for (int i = 0; i < 4; i++) {
                    u64 a = dup2(prow[i * TC + c]);
                    accO[i][0] = ffma2(a, v01.x, accO[i][0]);
                    accO[i][1] = ffma2(a, v01.y, accO[i][1]);
                    accO[i][2] = ffma2(a, v23.x, accO[i][2]);
                    accO[i][3] = ffma2(a, v23.y, accO[i][3]);
                }
            }
        }
    }

    // --- write partials ---
    __syncthreads();
    const int pbase = (ch * KV + kv) * NQ;
    if (tid < NQ) { g_pm[pbase + tid] = m_s[tid]; g_pl[pbase + tid] = l_s[tid]; }
    #pragma unroll
    for (int i = 0; i < 4; i++) {
        float* o = g_pout + (size_t)(pbase + q0 + i) * HD + t4;
        float2 a = unpk(accO[i][0]), b = unpk(accO[i][1]);
        *(float4*)o = make_float4(a.x, a.y, b.x, b.y);
        float2 c = unpk(accO[i][2]), d = unpk(accO[i][3]);
        *(float4*)(o + 64) = make_float4(c.x, c.y, d.x, d.y);
    }
}

// -------- kernel 2: logsumexp combine over chunks --------
__global__ void k_combine(float* __restrict__ out) {
    int row = blockIdx.x;        // kv*64 + q  == (head*16 + b) flattened
    int d = threadIdx.x;         // 0..127
    __shared__ float ms[NCH], ls[NCH];
    if (d < NCH) {
        ms[d] = g_pm[d * (KV * NQ) + row];
        ls[d] = g_pl[d * (KV * NQ) + row];
    }
    __syncthreads();
    float mstar = neg_inf();
    #pragma unroll
    for (int c = 0; c < NCH; c++) mstar = fmaxf(mstar, ms[c]);
    float num = 0.f, den = 0.f;
    for (int c = 0; c < NCH; c++) {
        float w = __expf(ms[c] - mstar);
        den += w * ls[c];
        num += w * g_pout[((size_t)c * (KV * NQ) + row) * HD + d];
    }
    out[(size_t)row * HD + d] = num / den;
}

extern "C" void kernel_launch(void* const* d_in, const int* in_sizes, int n_in,
                              void* d_out, int out_size) {
    const float* queries = (const float*)d_in[0];
    const float* keys    = (const float*)d_in[1];
    const float* ktc     = (const float*)d_in[2];
    const float* values  = (const float*)d_in[3];
    const float* vcache  = (const float*)d_in[4];
    const float* bias    = (const float*)d_in[5];
    const float* kqs     = (const float*)d_in[6];
    float* out = (float*)d_out;
    float* out_sk = out + NH * BATCH * HD;            // 65536
    float* out_sv = out_sk + KV * BATCH * HD;         // 81920

    k_scale<<<(KV * BATCH * HD + 255) / 256, 256>>>(keys, values, kqs, out_sk, out_sv);

    cudaFuncSetAttribute(k_attn, cudaFuncAttributeMaxDynamicSharedMemorySize, SMEM_BYTES);
    k_attn<<<dim3(NCH, KV), NTHR, SMEM_BYTES>>>(queries, ktc, vcache, bias, out_sk, out_sv);

    k_combine<<<KV * NQ, HD>>>(out);
}

// round 2
// speedup vs baseline: 1.0020x; 1.0020x over previous
#include <cuda_runtime.h>
#include <cstdint>

#define KV      8
#define GRP     4
#define NH      32
#define BATCH   16
#define HD      128
#define CTX     32768
#define CACHE   32736
#define NQ      64          // GRP*BATCH queries per kv head
#define TC      64          // ctx tile
#define NCH     37          // chunks -> 296 blocks = 2 waves-per-SM exactly
#define NT      (CTX / TC)  // 512 tiles total
#define NTHR    256

// -------- scratch (static device globals; no runtime allocation) --------
__device__ float g_pout[NCH * KV * NQ * HD];   // ~4.85 MB
__device__ float g_pm[NCH * KV * NQ];
__device__ float g_pl[NCH * KV * NQ];

typedef unsigned long long u64;

__device__ __forceinline__ u64 ffma2(u64 a, u64 b, u64 c) {
    u64 d; asm("fma.rn.f32x2 %0, %1, %2, %3;" : "=l"(d) : "l"(a), "l"(b), "l"(c)); return d;
}
__device__ __forceinline__ u64 fmul2(u64 a, u64 b) {
    u64 d; asm("mul.rn.f32x2 %0, %1, %2;" : "=l"(d) : "l"(a), "l"(b)); return d;
}
__device__ __forceinline__ u64 dup2(float x) {
    u64 r; asm("mov.b64 %0, {%1, %2};" : "=l"(r) : "f"(x), "f"(x)); return r;
}
__device__ __forceinline__ float2 unpk(u64 v) {
    float2 f; asm("mov.b64 {%0, %1}, %2;" : "=f"(f.x), "=f"(f.y) : "l"(v)); return f;
}
__device__ __forceinline__ float neg_inf() { return __int_as_float(0xff800000); }

// -------- kernel 0: scaled_keys / scaled_values outputs --------
__global__ void k_scale(const float* __restrict__ keys, const float* __restrict__ values,
                        const float* __restrict__ kq_scale,
                        float* __restrict__ out_sk, float* __restrict__ out_sv) {
    int i = blockIdx.x * blockDim.x + threadIdx.x;
    if (i < KV * BATCH * HD) {
        float s = kq_scale[0];
        out_sk[i] = keys[i] * s;
        out_sv[i] = fmaxf(values[i], -10000.0f);
    }
}

// -------- kernel 1: flash-decode partials over ctx chunks --------
// smem: Qt[HD][NQ] | Ks[HD][TC] (overlaid by Ps[NQ][TC]) | Vs[TC][HD] | m,l,scale[NQ]
#define SMEM_BYTES ((8192 * 3 + 192) * 4)

__global__ void __launch_bounds__(NTHR, 2)
k_attn(const float* __restrict__ q_g, const float* __restrict__ ktc,
       const float* __restrict__ vc, const float* __restrict__ bias,
       const float* __restrict__ sk, const float* __restrict__ sv) {
    extern __shared__ float sm[];
    float* Qt   = sm;            // [d][q]
    float* Ks   = sm + 8192;     // [d][c]
    float* Vs   = sm + 16384;    // [c][d]
    float* m_s  = sm + 24576;
    float* l_s  = sm + 24640;
    float* sc_s = sm + 24704;
    float* Ps   = Ks;            // overlay: [q][c]

    const int ch = blockIdx.x, kv = blockIdx.y;
    const int tid = threadIdx.x;
    const int ty = tid >> 4, tx = tid & 15;
    const int q0 = ty << 2, t4 = tx << 2;

    // load Q transposed: Qt[d][q], q = g*16+b
    const float* qb = q_g + (size_t)kv * (GRP * BATCH * HD);
    #pragma unroll
    for (int r = 0; r < 32; r++) {
        int idx = tid + r * NTHR;          // 0..8191
        int q = idx >> 7, d = idx & 127;
        Qt[d * NQ + q] = qb[idx];
    }
    if (tid < NQ) { m_s[tid] = neg_inf(); l_s[tid] = 0.0f; }

    u64 accO[4][4];
    #pragma unroll
    for (int i = 0; i < 4; i++)
        #pragma unroll
        for (int k = 0; k < 4; k++) accO[i][k] = 0ull;

    const int tb = (ch * NT) / NCH, te = ((ch + 1) * NT) / NCH;
    const float* kbase = ktc + (size_t)kv * HD * CACHE;
    const float* vbase = vc  + (size_t)kv * CACHE * HD;
    const float* skb   = sk  + kv * BATCH * HD;
    const float* svb   = sv  + kv * BATCH * HD;

    for (int t = tb; t < te; t++) {
        const int c0 = t * TC;
        __syncthreads();   // prev GEMM2 done with Vs/Ps

        // --- load K tile (coalesced rows of K^T cache), zero-fill OOB ---
        #pragma unroll
        for (int r = 0; r < 8; r++) {
            int idx = tid + r * NTHR;                 // float4 units, 0..2047
            int d = idx >> 4, cl4 = (idx & 15) << 2;
            int c = c0 + cl4;
            float4 v = (c < CACHE) ? *(const float4*)(kbase + (size_t)d * CACHE + c)
                                   : make_float4(0.f, 0.f, 0.f, 0.f);
            *(float4*)(Ks + d * TC + cl4) = v;
        }
        // --- load V tile ---
        #pragma unroll
        for (int r = 0; r < 8; r++) {
            int idx = tid + r * NTHR;
            int cl = idx >> 5, d4 = (idx & 31) << 2;
            int c = c0 + cl;
            float4 v = (c < CACHE) ? *(const float4*)(vbase + (size_t)c * HD + d4)
                                   : make_float4(0.f, 0.f, 0.f, 0.f);
            *(float4*)(Vs + cl * HD + d4) = v;
        }
        // --- overlay the 16 new tokens (last tile only) ---
        if (c0 + TC > CACHE) {
            int off = CACHE - c0;                      // 32
            for (int idx = tid; idx < BATCH * HD; idx += NTHR) {
                int cn = idx >> 7, d = idx & 127;
                Ks[d * TC + off + cn] = skb[idx];
            }
            for (int idx = tid; idx < BATCH * (HD / 4); idx += NTHR) {
                int cn = idx >> 5, d4 = (idx & 31) << 2;
                *(float4*)(Vs + (off + cn) * HD + d4) = *(const float4*)(svb + cn * HD + d4);
            }
        }
        __syncthreads();

        // --- GEMM1: S[4q][4c] via f32x2 (pairs over c) ---
        u64 accS[4][2];
        #pragma unroll
        for (int i = 0; i < 4; i++) { accS[i][0] = 0ull; accS[i][1] = 0ull; }
        {
            const float* qrow = Qt + q0;
            const float* krow = Ks + t4;
            #pragma unroll 8
            for (int d = 0; d < HD; d++) {
                float4 a = *(const float4*)(qrow + d * NQ);
                ulonglong2 b = *(const ulonglong2*)(krow + d * TC);
                u64 a0 = dup2(a.x), a1 = dup2(a.y), a2 = dup2(a.z), a3 = dup2(a.w);
                accS[0][0] = ffma2(a0, b.x, accS[0][0]); accS[0][1] = ffma2(a0, b.y, accS[0][1]);
                accS[1][0] = ffma2(a1, b.x, accS[1][0]); accS[1][1] = ffma2(a1, b.y, accS[1][1]);
                accS[2][0] = ffma2(a2, b.x, accS[2][0]); accS[2][1] = ffma2(a2, b.y, accS[2][1]);
                accS[3][0] = ffma2(a3, b.x, accS[3][0]); accS[3][1] = ffma2(a3, b.y, accS[3][1]);
            }
        }
        __syncthreads();   // GEMM1 done reading Ks -> safe to overwrite with Ps

        // --- online softmax epilogue ---
        float s[4][4];
        #pragma unroll
        for (int i = 0; i < 4; i++) {
            float2 p0 = unpk(accS[i][0]), p1 = unpk(accS[i][1]);
            s[i][0] = p0.x; s[i][1] = p0.y; s[i][2] = p1.x; s[i][3] = p1.y;
        }
        if (c0 + TC > CACHE) {   // bias is exactly 0 everywhere else; read real input here
            #pragma unroll
            for (int i = 0; i < 4; i++) {
                int b = (q0 + i) & 15;
                #pragma unroll
                for (int j = 0; j < 4; j++) s[i][j] += bias[(size_t)b * CTX + c0 + t4 + j];
            }
        }
        float mold[4], lold[4], mnew[4], scl[4], lsum[4];
        float pr[4][4];
        #pragma unroll
        for (int i = 0; i < 4; i++) {
            int q = q0 + i;
            float mx = fmaxf(fmaxf(s[i][0], s[i][1]), fmaxf(s[i][2], s[i][3]));
            #pragma unroll
            for (int off = 8; off >= 1; off >>= 1)
                mx = fmaxf(mx, __shfl_xor_sync(0xffffffffu, mx, off, 16));
            mold[i] = m_s[q]; lold[i] = l_s[q];
            mnew[i] = fmaxf(mold[i], mx);
            float ls = 0.f;
            #pragma unroll
            for (int j = 0; j < 4; j++) { pr[i][j] = __expf(s[i][j] - mnew[i]); ls += pr[i][j]; }
            #pragma unroll
            for (int off = 8; off >= 1; off >>= 1)
                ls += __shfl_xor_sync(0xffffffffu, ls, off, 16);
            lsum[i] = ls;
            scl[i] = __expf(mold[i] - mnew[i]);    // exp(-inf)=0 on first tile
        }
        __syncwarp();  // all lanes read m_s/l_s before any lane writes
        #pragma unroll
        for (int i = 0; i < 4; i++) {
            int q = q0 + i;
            m_s[q]  = mnew[i];                     // identical value from all 16 lanes
            l_s[q]  = lold[i] * scl[i] + lsum[i];
            sc_s[q] = scl[i];
            *(float4*)(Ps + q * TC + t4) = make_float4(pr[i][0], pr[i][1], pr[i][2], pr[i][3]);
        }
        __syncthreads();

        // --- GEMM2: O[4q][8d] += P * V, f32x2 (pairs over d) ---
        #pragma unroll
        for (int i = 0; i < 4; i++) {
            u64 s2 = dup2(sc_s[q0 + i]);
            #pragma unroll
            for (int k = 0; k < 4; k++) accO[i][k] = fmul2(accO[i][k], s2);
        }
        {
            const float* vcol = Vs + t4;
            const float* prow = Ps + q0 * TC;
            #pragma unroll 4
            for (int c = 0; c < TC; c++) {
                ulonglong2 v01 = *(const ulonglong2*)(vcol + c * HD);
                ulonglong2 v23 = *(const ulonglong2*)(vcol + c * HD + 64);
                #pragma unroll
                for (int i = 0; i < 4; i++) {
                    u64 a = dup2(prow[i * TC + c]);
                    accO[i][0] = ffma2(a, v01.x, accO[i][0]);
                    accO[i][1] = ffma2(a, v01.y, accO[i][1]);
                    accO[i][2] = ffma2(a, v23.x, accO[i][2]);
                    accO[i][3] = ffma2(a, v23.y, accO[i][3]);
                }
            }
        }
    }

    // --- write partials ---
    __syncthreads();
    const int pbase = (ch * KV + kv) * NQ;
    if (tid < NQ) { g_pm[pbase + tid] = m_s[tid]; g_pl[pbase + tid] = l_s[tid]; }
    #pragma unroll
    for (int i = 0; i < 4; i++) {
        float* o = g_pout + (size_t)(pbase + q0 + i) * HD + t4;
        float2 a = unpk(accO[i][0]), b = unpk(accO[i][1]);
        *(float4*)o = make_float4(a.x, a.y, b.x, b.y);
        float2 c = unpk(accO[i][2]), d = unpk(accO[i][3]);
        *(float4*)(o + 64) = make_float4(c.x, c.y, d.x, d.y);
    }
}

// -------- kernel 2: logsumexp combine over chunks --------
__global__ void k_combine(float* __restrict__ out) {
    int row = blockIdx.x;        // kv*64 + q  == (head*16 + b) flattened
    int d = threadIdx.x;         // 0..127
    __shared__ float ms[NCH], ls[NCH];
    if (d < NCH) {
        ms[d] = g_pm[d * (KV * NQ) + row];
        ls[d] = g_pl[d * (KV * NQ) + row];
    }
    __syncthreads();
    float mstar = neg_inf();
    #pragma unroll
    for (int c = 0; c < NCH; c++) mstar = fmaxf(mstar, ms[c]);
    float num = 0.f, den = 0.f;
    for (int c = 0; c < NCH; c++) {
        float w = __expf(ms[c] - mstar);
        den += w * ls[c];
        num += w * g_pout[((size_t)c * (KV * NQ) + row) * HD + d];
    }
    out[(size_t)row * HD + d] = num / den;
}

extern "C" void kernel_launch(void* const* d_in, const int* in_sizes, int n_in,
                              void* d_out, int out_size) {
    const float* queries = (const float*)d_in[0];
    const float* keys    = (const float*)d_in[1];
    const float* ktc     = (const float*)d_in[2];
    const float* values  = (const float*)d_in[3];
    const float* vcache  = (const float*)d_in[4];
    const float* bias    = (const float*)d_in[5];
    const float* kqs     = (const float*)d_in[6];
    float* out = (float*)d_out;
    float* out_sk = out + NH * BATCH * HD;            // 65536
    float* out_sv = out_sk + KV * BATCH * HD;         // 81920

    k_scale<<<(KV * BATCH * HD + 255) / 256, 256>>>(keys, values, kqs, out_sk, out_sv);

    cudaFuncSetAttribute(k_attn, cudaFuncAttributeMaxDynamicSharedMemorySize, SMEM_BYTES);
    k_attn<<<dim3(NCH, KV), NTHR, SMEM_BYTES>>>(queries, ktc, vcache, bias, out_sk, out_sv);

    k_combine<<<KV * NQ, HD>>>(out);
}

// round 3
// speedup vs baseline: 1.6489x; 1.6456x over previous
#include <cuda_runtime.h>
#include <cuda_bf16.h>
#include <cstdint>

#define KV      8
#define GRP     4
#define NH      32
#define BATCH   16
#define HD      128
#define CTX     32768
#define CACHE   32736
#define NQ      64
#define TC      128
#define NCH     18           // 18*8 = 144 blocks = one wave on 148 SMs
#define NT      (CTX / TC)   // 256 tiles
#define NTHR    512
#define LDT     136          // smem pitch in bf16 (128 + 8 pad -> conflict-free ldmatrix)

// ---- scratch ----
__device__ float g_pout[NCH * KV * NQ * HD];
__device__ float g_pm[NCH * KV * NQ];
__device__ float g_pl[NCH * KV * NQ];

// ---- smem byte offsets ----
#define QH_OFF   0                         // 64*136*2  = 17408
#define QL_OFF   17408
#define KH_OFF   34816                     // 128*136*2 = 34816
#define KL_OFF   69632
#define VH_OFF   104448
#define VL_OFF   139264
#define PH_OFF   174080                    // 64*136*2
#define PL_OFF   191488
#define RMAX_OFF 208896                    // 4*64*4
#define RSUM_OFF 209920
#define MS_OFF   210944
#define LS_OFF   211200
#define SMEM_BYTES 211456

__device__ __forceinline__ float neg_inf() { return __int_as_float(0xff800000); }

// split x into bf16 hi + bf16 lo, two elements at a time, packed for smem
__device__ __forceinline__ void split_pack(float x0, float x1, uint32_t& hi, uint32_t& lo) {
    asm("cvt.rn.bf16x2.f32 %0, %1, %2;" : "=r"(hi) : "f"(x1), "f"(x0));   // upper=x1, lower=x0
    float h0 = __uint_as_float(hi << 16);
    float h1 = __uint_as_float(hi & 0xffff0000u);
    float r0 = x0 - h0, r1 = x1 - h1;
    asm("cvt.rn.bf16x2.f32 %0, %1, %2;" : "=r"(lo) : "f"(r1), "f"(r0));
}
__device__ __forceinline__ void split1(float x, __nv_bfloat16& h, __nv_bfloat16& l) {
    h = __float2bfloat16(x);
    l = __float2bfloat16(x - __bfloat162float(h));
}

__device__ __forceinline__ void ldsm4(uint32_t* r, uint32_t addr) {
    asm volatile("ldmatrix.sync.aligned.m8n8.x4.shared.b16 {%0,%1,%2,%3}, [%4];"
                 : "=r"(r[0]), "=r"(r[1]), "=r"(r[2]), "=r"(r[3]) : "r"(addr));
}
__device__ __forceinline__ void ldsm4t(uint32_t* r, uint32_t addr) {
    asm volatile("ldmatrix.sync.aligned.m8n8.x4.trans.shared.b16 {%0,%1,%2,%3}, [%4];"
                 : "=r"(r[0]), "=r"(r[1]), "=r"(r[2]), "=r"(r[3]) : "r"(addr));
}
__device__ __forceinline__ void mma16816(float* c, const uint32_t* a, uint32_t b0, uint32_t b1) {
    asm volatile("mma.sync.aligned.m16n8k16.row.col.f32.bf16.bf16.f32 "
                 "{%0,%1,%2,%3}, {%4,%5,%6,%7}, {%8,%9}, {%0,%1,%2,%3};"
                 : "+f"(c[0]), "+f"(c[1]), "+f"(c[2]), "+f"(c[3])
                 : "r"(a[0]), "r"(a[1]), "r"(a[2]), "r"(a[3]), "r"(b0), "r"(b1));
}

// -------- kernel 0: scaled_keys / scaled_values outputs --------
__global__ void k_scale(const float* __restrict__ keys, const float* __restrict__ values,
                        const float* __restrict__ kq_scale,
                        float* __restrict__ out_sk, float* __restrict__ out_sv) {
    int i = blockIdx.x * blockDim.x + threadIdx.x;
    if (i < KV * BATCH * HD) {
        float s = kq_scale[0];
        out_sk[i] = keys[i] * s;
        out_sv[i] = fmaxf(values[i], -10000.0f);
    }
}

// -------- kernel 1: flash-decode via split-bf16 HMMA --------
__global__ void __launch_bounds__(NTHR, 1)
k_attn(const float* __restrict__ q_g, const float* __restrict__ ktc,
       const float* __restrict__ vc, const float* __restrict__ bias,
       const float* __restrict__ sk, const float* __restrict__ sv) {
    extern __shared__ char smc[];
    uint32_t sb = (uint32_t)__cvta_generic_to_shared(smc);
    float* red_max = (float*)(smc + RMAX_OFF);   // [4 ngroups][64 rows]
    float* red_sum = (float*)(smc + RSUM_OFF);
    float* m_s = (float*)(smc + MS_OFF);
    float* l_s = (float*)(smc + LS_OFF);

    const int ch = blockIdx.x, kv = blockIdx.y;
    const int tid = threadIdx.x;
    const int wid = tid >> 5, lane = tid & 31;
    const int mg = wid & 3, ng = wid >> 2;
    const int m0 = mg << 4, n0 = ng << 5;
    const int lm = lane & 15, lh = lane >> 4, quad = lane >> 2, qt = lane & 3;
    const int r0 = m0 + quad, r1 = r0 + 8;

    // ---- load Q, split to bf16 hi/lo ----
    const float* qb = q_g + (size_t)kv * (NQ * HD);
    #pragma unroll
    for (int r = 0; r < 4; r++) {
        int i4 = tid + r * NTHR;                 // float4 units, 0..2047
        int m = i4 >> 5, k4 = (i4 & 31) << 2;
        float4 v = *(const float4*)(qb + m * HD + k4);
        uint32_t h0, l0, h1, l1;
        split_pack(v.x, v.y, h0, l0); split_pack(v.z, v.w, h1, l1);
        int bo = (m * LDT + k4) * 2;
        *(uint2*)(smc + QH_OFF + bo) = make_uint2(h0, h1);
        *(uint2*)(smc + QL_OFF + bo) = make_uint2(l0, l1);
    }
    if (tid < NQ) { m_s[tid] = neg_inf(); l_s[tid] = 0.0f; }

    float accO[4][4];
    #pragma unroll
    for (int j = 0; j < 4; j++)
        #pragma unroll
        for (int i = 0; i < 4; i++) accO[j][i] = 0.0f;

    // ---- precomputed ldmatrix base addresses (constant across tiles) ----
    const uint32_t aQh = sb + QH_OFF + (uint32_t)((m0 + lm) * LDT + (lh << 3)) * 2;
    const uint32_t aQl = aQh + (QL_OFF - QH_OFF);
    const uint32_t bKh = sb + KH_OFF + (uint32_t)(lm * LDT + n0 + (lh << 3)) * 2;
    const uint32_t bKl = bKh + (KL_OFF - KH_OFF);
    const uint32_t aPh = sb + PH_OFF + (uint32_t)((m0 + lm) * LDT + (lh << 3)) * 2;
    const uint32_t aPl = aPh + (PL_OFF - PH_OFF);
    const uint32_t bVh = sb + VH_OFF + (uint32_t)(lm * LDT + n0 + (lh << 3)) * 2;
    const uint32_t bVl = bVh + (VL_OFF - VH_OFF);
    const uint32_t KSTEP = 16 * LDT * 2;         // 16 k-rows per mma step

    const int tb = (ch * NT) / NCH, te = ((ch + 1) * NT) / NCH;
    const float* kbase = ktc + (size_t)kv * HD * CACHE;
    const float* vbase = vc  + (size_t)kv * CACHE * HD;
    const float* skb   = sk  + kv * BATCH * HD;
    const float* svb   = sv  + kv * BATCH * HD;

    for (int t = tb; t < te; t++) {
        const int c0 = t * TC;
        __syncthreads();   // prev GEMM2 done with P/V; prev GEMM1 done with K

        // ---- load + split K tile: Ks[k=d][c], pitch LDT ----
        #pragma unroll
        for (int r = 0; r < 8; r++) {
            int i4 = tid + r * NTHR;             // 0..4095 float4 units
            int k = i4 >> 5, c4 = (i4 & 31) << 2;
            int c = c0 + c4;
            float4 v = (c < CACHE) ? *(const float4*)(kbase + (size_t)k * CACHE + c)
                                   : make_float4(0.f, 0.f, 0.f, 0.f);
            uint32_t h0, l0, h1, l1;
            split_pack(v.x, v.y, h0, l0); split_pack(v.z, v.w, h1, l1);
            int bo = (k * LDT + c4) * 2;
            *(uint2*)(smc + KH_OFF + bo) = make_uint2(h0, h1);
            *(uint2*)(smc + KL_OFF + bo) = make_uint2(l0, l1);
        }
        // ---- load + split V tile: Vs[c][d] ----
        #pragma unroll
        for (int r = 0; r < 8; r++) {
            int i4 = tid + r * NTHR;
            int cl = i4 >> 5, d4 = (i4 & 31) << 2;
            int c = c0 + cl;
            float4 v = (c < CACHE) ? *(const float4*)(vbase + (size_t)c * HD + d4)
                                   : make_float4(0.f, 0.f, 0.f, 0.f);
            uint32_t h0, l0, h1, l1;
            split_pack(v.x, v.y, h0, l0); split_pack(v.z, v.w, h1, l1);
            int bo = (cl * LDT + d4) * 2;
            *(uint2*)(smc + VH_OFF + bo) = make_uint2(h0, h1);
            *(uint2*)(smc + VL_OFF + bo) = make_uint2(l0, l1);
        }
        // ---- overlay 16 new tokens on the last tile ----
        if (t == NT - 1) {
            int cl0 = CACHE - c0;
            for (int i = tid; i < BATCH * HD; i += NTHR) {
                int b = i >> 7, d = i & 127;
                __nv_bfloat16 h, l;
                split1(skb[i], h, l);
                *(__nv_bfloat16*)(smc + KH_OFF + (d * LDT + cl0 + b) * 2) = h;
                *(__nv_bfloat16*)(smc + KL_OFF + (d * LDT + cl0 + b) * 2) = l;
                split1(svb[i], h, l);
                *(__nv_bfloat16*)(smc + VH_OFF + ((cl0 + b) * LDT + d) * 2) = h;
                *(__nv_bfloat16*)(smc + VL_OFF + ((cl0 + b) * LDT + d) * 2) = l;
            }
        }
        __syncthreads();

        // ---- GEMM1: S[64, 128] = Q * K  (3-pass split) ----
        float accS[4][4];
        #pragma unroll
        for (int j = 0; j < 4; j++)
            #pragma unroll
            for (int i = 0; i < 4; i++) accS[j][i] = 0.0f;
        {
            uint32_t aa = aQh, bh = bKh, bl = bKl;
            #pragma unroll
            for (int kk = 0; kk < 8; kk++) {
                uint32_t a[4], b0[4], b1[4], e0[4], e1[4];
                ldsm4(a, aa);
                ldsm4t(b0, bh); ldsm4t(b1, bh + 32);
                ldsm4t(e0, bl); ldsm4t(e1, bl + 32);
                mma16816(accS[0], a, b0[0], b0[1]); mma16816(accS[1], a, b0[2], b0[3]);
                mma16816(accS[2], a, b1[0], b1[1]); mma16816(accS[3], a, b1[2], b1[3]);
                mma16816(accS[0], a, e0[0], e0[1]); mma16816(accS[1], a, e0[2], e0[3]);
                mma16816(accS[2], a, e1[0], e1[1]); mma16816(accS[3], a, e1[2], e1[3]);
                aa += 32; bh += KSTEP; bl += KSTEP;
            }
            aa = aQl; bh = bKh;
            #pragma unroll
            for (int kk = 0; kk < 8; kk++) {
                uint32_t a[4], b0[4], b1[4];
                ldsm4(a, aa);
                ldsm4t(b0, bh); ldsm4t(b1, bh + 32);
                mma16816(accS[0], a, b0[0], b0[1]); mma16816(accS[1], a, b0[2], b0[3]);
                mma16816(accS[2], a, b1[0], b1[1]); mma16816(accS[3], a, b1[2], b1[3]);
                aa += 32; bh += KSTEP;
            }
        }

        // ---- bias on last tile only (zero everywhere else by construction) ----
        if (t == NT - 1) {
            #pragma unroll
            for (int j = 0; j < 4; j++) {
                int cg = c0 + n0 + 8 * j + 2 * qt;
                const float* bp0 = bias + (size_t)(r0 & 15) * CTX + cg;
                const float* bp1 = bias + (size_t)(r1 & 15) * CTX + cg;
                accS[j][0] += bp0[0]; accS[j][1] += bp0[1];
                accS[j][2] += bp1[0]; accS[j][3] += bp1[1];
            }
        }

        // ---- online softmax (cross-warp over 4 n-groups) ----
        float mx0 = neg_inf(), mx1 = neg_inf();
        #pragma unroll
        for (int j = 0; j < 4; j++) {
            mx0 = fmaxf(mx0, fmaxf(accS[j][0], accS[j][1]));
            mx1 = fmaxf(mx1, fmaxf(accS[j][2], accS[j][3]));
        }
        mx0 = fmaxf(mx0, __shfl_xor_sync(0xffffffffu, mx0, 1));
        mx0 = fmaxf(mx0, __shfl_xor_sync(0xffffffffu, mx0, 2));
        mx1 = fmaxf(mx1, __shfl_xor_sync(0xffffffffu, mx1, 1));
        mx1 = fmaxf(mx1, __shfl_xor_sync(0xffffffffu, mx1, 2));
        if (qt == 0) { red_max[ng * 64 + r0] = mx0; red_max[ng * 64 + r1] = mx1; }
        __syncthreads();

        float mt0 = fmaxf(fmaxf(red_max[r0], red_max[64 + r0]),
                          fmaxf(red_max[128 + r0], red_max[192 + r0]));
        float mt1 = fmaxf(fmaxf(red_max[r1], red_max[64 + r1]),
                          fmaxf(red_max[128 + r1], red_max[192 + r1]));
        float mold0 = m_s[r0], mold1 = m_s[r1];
        float mnew0 = fmaxf(mold0, mt0), mnew1 = fmaxf(mold1, mt1);
        float scl0 = __expf(mold0 - mnew0), scl1 = __expf(mold1 - mnew1);

        float sum0 = 0.f, sum1 = 0.f;
        #pragma unroll
        for (int j = 0; j < 4; j++) {
            float p00 = __expf(accS[j][0] - mnew0);
            float p01 = __expf(accS[j][1] - mnew0);
            float p10 = __expf(accS[j][2] - mnew1);
            float p11 = __expf(accS[j][3] - mnew1);
            sum0 += p00 + p01; sum1 += p10 + p11;
            uint32_t h, l;
            int bo0 = (r0 * LDT + n0 + 8 * j + 2 * qt) * 2;
            split_pack(p00, p01, h, l);
            *(uint32_t*)(smc + PH_OFF + bo0) = h;
            *(uint32_t*)(smc + PL_OFF + bo0) = l;
            int bo1 = (r1 * LDT + n0 + 8 * j + 2 * qt) * 2;
            split_pack(p10, p11, h, l);
            *(uint32_t*)(smc + PH_OFF + bo1) = h;
            *(uint32_t*)(smc + PL_OFF + bo1) = l;
        }
        sum0 += __shfl_xor_sync(0xffffffffu, sum0, 1);
        sum0 += __shfl_xor_sync(0xffffffffu, sum0, 2);
        sum1 += __shfl_xor_sync(0xffffffffu, sum1, 1);
        sum1 += __shfl_xor_sync(0xffffffffu, sum1, 2);
        if (qt == 0) { red_sum[ng * 64 + r0] = sum0; red_sum[ng * 64 + r1] = sum1; }
        __syncthreads();

        if (wid < 4 && qt == 0) {   // one owner set per row updates running stats
            float s0 = red_sum[r0] + red_sum[64 + r0] + red_sum[128 + r0] + red_sum[192 + r0];
            float s1 = red_sum[r1] + red_sum[64 + r1] + red_sum[128 + r1] + red_sum[192 + r1];
            l_s[r0] = l_s[r0] * scl0 + s0;  m_s[r0] = mnew0;
            l_s[r1] = l_s[r1] * scl1 + s1;  m_s[r1] = mnew1;
        }

        // ---- rescale accO, then GEMM2: O += P * V (3-pass split) ----
        #pragma unroll
        for (int j = 0; j < 4; j++) {
            accO[j][0] *= scl0; accO[j][1] *= scl0;
            accO[j][2] *= scl1; accO[j][3] *= scl1;
        }
        {
            uint32_t aa = aPh, bh = bVh, bl = bVl;
            #pragma unroll
            for (int kk = 0; kk < 8; kk++) {
                uint32_t a[4], b0[4], b1[4], e0[4], e1[4];
                ldsm4(a, aa);
                ldsm4t(b0, bh); ldsm4t(b1, bh + 32);
                ldsm4t(e0, bl); ldsm4t(e1, bl + 32);
                mma16816(accO[0], a, b0[0], b0[1]); mma16816(accO[1], a, b0[2], b0[3]);
                mma16816(accO[2], a, b1[0], b1[1]); mma16816(accO[3], a, b1[2], b1[3]);
                mma16816(accO[0], a, e0[0], e0[1]); mma16816(accO[1], a, e0[2], e0[3]);
                mma16816(accO[2], a, e1[0], e1[1]); mma16816(accO[3], a, e1[2], e1[3]);
                aa += 32; bh += KSTEP; bl += KSTEP;
            }
            aa = aPl; bh = bVh;
            #pragma unroll
            for (int kk = 0; kk < 8; kk++) {
                uint32_t a[4], b0[4], b1[4];
                ldsm4(a, aa);
                ldsm4t(b0, bh); ldsm4t(b1, bh + 32);
                mma16816(accO[0], a, b0[0], b0[1]); mma16816(accO[1], a, b0[2], b0[3]);
                mma16816(accO[2], a, b1[0], b1[1]); mma16816(accO[3], a, b1[2], b1[3]);
                aa += 32; bh += KSTEP;
            }
        }
    }

    // ---- write partials ----
    __syncthreads();
    const int pbase = (ch * KV + kv) * NQ;
    if (tid < NQ) { g_pm[pbase + tid] = m_s[tid]; g_pl[pbase + tid] = l_s[tid]; }
    #pragma unroll
    for (int j = 0; j < 4; j++) {
        int d = n0 + 8 * j + 2 * qt;
        *(float2*)&g_pout[(size_t)(pbase + r0) * HD + d] = make_float2(accO[j][0], accO[j][1]);
        *(float2*)&g_pout[(size_t)(pbase + r1) * HD + d] = make_float2(accO[j][2], accO[j][3]);
    }
}

// -------- kernel 2: logsumexp combine over chunks --------
__global__ void k_combine(float* __restrict__ out) {
    int row = blockIdx.x;        // kv*64 + q
    int d = threadIdx.x;         // 0..127
    __shared__ float ms[NCH], ls[NCH];
    if (d < NCH) {
        ms[d] = g_pm[d * (KV * NQ) + row];
        ls[d] = g_pl[d * (KV * NQ) + row];
    }
    __syncthreads();
    float mstar = neg_inf();
    #pragma unroll
    for (int c = 0; c < NCH; c++) mstar = fmaxf(mstar, ms[c]);
    float num = 0.f, den = 0.f;
    for (int c = 0; c < NCH; c++) {
        float w = __expf(ms[c] - mstar);
        den += w * ls[c];
        num += w * g_pout[((size_t)c * (KV * NQ) + row) * HD + d];
    }
    out[(size_t)row * HD + d] = num / den;
}

extern "C" void kernel_launch(void* const* d_in, const int* in_sizes, int n_in,
                              void* d_out, int out_size) {
    const float* queries = (const float*)d_in[0];
    const float* keys    = (const float*)d_in[1];
    const float* ktc     = (const float*)d_in[2];
    const float* values  = (const float*)d_in[3];
    const float* vcache  = (const float*)d_in[4];
    const float* bias    = (const float*)d_in[5];
    const float* kqs     = (const float*)d_in[6];
    float* out = (float*)d_out;
    float* out_sk = out + NH * BATCH * HD;            // 65536
    float* out_sv = out_sk + KV * BATCH * HD;         // 81920

    k_scale<<<(KV * BATCH * HD + 255) / 256, 256>>>(keys, values, kqs, out_sk, out_sv);

    cudaFuncSetAttribute(k_attn, cudaFuncAttributeMaxDynamicSharedMemorySize, SMEM_BYTES);
    k_attn<<<dim3(NCH, KV), NTHR, SMEM_BYTES>>>(queries, ktc, vcache, bias, out_sk, out_sv);

    k_combine<<<KV * NQ, HD>>>(out);
}

// round 4
// speedup vs baseline: 1.8492x; 1.1215x over previous
#include <cuda_runtime.h>
#include <cuda_bf16.h>
#include <cstdint>

#define KV      8
#define NH      32
#define BATCH   16
#define HD      128
#define CTX     32768
#define CACHE   32736
#define NQ      64
#define TC      64
#define NCH     37           // 37*8 = 296 blocks = 2 CTAs/SM * 148 SMs, one wave
#define NT      (CTX / TC)   // 512 tiles
#define NTHR    256
#define LDQ     136          // pitch (bf16) for Q and V tiles: 128 + 8 pad
#define LDK     72           // pitch (bf16) for K and P tiles: 64 + 8 pad

// ---- scratch ----
__device__ float g_pout[NCH * KV * NQ * HD];
__device__ float g_pm[NCH * KV * NQ];
__device__ float g_pl[NCH * KV * NQ];

// ---- smem byte offsets (per CTA total 108032 B -> 2 CTAs/SM) ----
#define QH_OFF   0            // 64*136*2 = 17408
#define QL_OFF   17408
#define KH_OFF   34816        // 128*72*2 = 18432
#define KL_OFF   53248
#define VH_OFF   71680        // 64*136*2 = 17408
#define VL_OFF   89088
#define PH_OFF   KH_OFF       // P overlays K (GEMM1 done with K before P written)
#define PL_OFF   KL_OFF
#define RMAX_OFF 106496       // [2][64] f32
#define RSUM_OFF 107008
#define MS_OFF   107520
#define LS_OFF   107776
#define SMEM_BYTES 108032

__device__ __forceinline__ float neg_inf() { return __int_as_float(0xff800000); }

__device__ __forceinline__ void split_pack(float x0, float x1, uint32_t& hi, uint32_t& lo) {
    asm("cvt.rn.bf16x2.f32 %0, %1, %2;" : "=r"(hi) : "f"(x1), "f"(x0));
    float h0 = __uint_as_float(hi << 16);
    float h1 = __uint_as_float(hi & 0xffff0000u);
    float r0 = x0 - h0, r1 = x1 - h1;
    asm("cvt.rn.bf16x2.f32 %0, %1, %2;" : "=r"(lo) : "f"(r1), "f"(r0));
}
__device__ __forceinline__ void split1(float x, __nv_bfloat16& h, __nv_bfloat16& l) {
    h = __float2bfloat16(x);
    l = __float2bfloat16(x - __bfloat162float(h));
}
__device__ __forceinline__ void ldsm4(uint32_t* r, uint32_t addr) {
    asm volatile("ldmatrix.sync.aligned.m8n8.x4.shared.b16 {%0,%1,%2,%3}, [%4];"
                 : "=r"(r[0]), "=r"(r[1]), "=r"(r[2]), "=r"(r[3]) : "r"(addr));
}
__device__ __forceinline__ void ldsm4t(uint32_t* r, uint32_t addr) {
    asm volatile("ldmatrix.sync.aligned.m8n8.x4.trans.shared.b16 {%0,%1,%2,%3}, [%4];"
                 : "=r"(r[0]), "=r"(r[1]), "=r"(r[2]), "=r"(r[3]) : "r"(addr));
}
__device__ __forceinline__ void mma16816(float* c, const uint32_t* a, uint32_t b0, uint32_t b1) {
    asm volatile("mma.sync.aligned.m16n8k16.row.col.f32.bf16.bf16.f32 "
                 "{%0,%1,%2,%3}, {%4,%5,%6,%7}, {%8,%9}, {%0,%1,%2,%3};"
                 : "+f"(c[0]), "+f"(c[1]), "+f"(c[2]), "+f"(c[3])
                 : "r"(a[0]), "r"(a[1]), "r"(a[2]), "r"(a[3]), "r"(b0), "r"(b1));
}

// -------- kernel 1: flash-decode via split-bf16 HMMA, 2 CTAs/SM --------
__global__ void __launch_bounds__(NTHR, 2)
k_attn(const float* __restrict__ q_g, const float* __restrict__ ktc,
       const float* __restrict__ vc, const float* __restrict__ bias,
       const float* __restrict__ keys, const float* __restrict__ values,
       const float* __restrict__ kqs,
       float* __restrict__ out_sk, float* __restrict__ out_sv) {
    extern __shared__ char smc[];
    uint32_t sb = (uint32_t)__cvta_generic_to_shared(smc);
    float* red_max = (float*)(smc + RMAX_OFF);   // [2 ngroups][64 rows]
    float* red_sum = (float*)(smc + RSUM_OFF);
    float* m_s = (float*)(smc + MS_OFF);
    float* l_s = (float*)(smc + LS_OFF);

    const int ch = blockIdx.x, kv = blockIdx.y;
    const int tid = threadIdx.x;
    const int wid = tid >> 5, lane = tid & 31;
    const int mg = wid & 3, ng = wid >> 2;       // 4 m-groups x 2 n-groups
    const int m0 = mg << 4, n0 = ng << 5;        // GEMM1 n-tile = 32
    const int lm = lane & 15, lh = lane >> 4, quad = lane >> 2, qt = lane & 3;
    const int r0 = m0 + quad, r1 = r0 + 8;

    // ---- load Q, split to bf16 hi/lo ----
    const float* qb = q_g + (size_t)kv * (NQ * HD);
    #pragma unroll
    for (int r = 0; r < 8; r++) {
        int i4 = tid + r * NTHR;                 // 0..2047 float4 units
        int m = i4 >> 5, k4 = (i4 & 31) << 2;
        float4 v = *(const float4*)(qb + m * HD + k4);
        uint32_t h0, l0, h1, l1;
        split_pack(v.x, v.y, h0, l0); split_pack(v.z, v.w, h1, l1);
        int bo = (m * LDQ + k4) * 2;
        *(uint2*)(smc + QH_OFF + bo) = make_uint2(h0, h1);
        *(uint2*)(smc + QL_OFF + bo) = make_uint2(l0, l1);
    }
    if (tid < NQ) { m_s[tid] = neg_inf(); l_s[tid] = 0.0f; }

    float accO[8][4];
    #pragma unroll
    for (int j = 0; j < 8; j++)
        #pragma unroll
        for (int i = 0; i < 4; i++) accO[j][i] = 0.0f;

    // ---- ldmatrix base addresses (tile-invariant) ----
    const uint32_t aQh = sb + QH_OFF + (uint32_t)((m0 + lm) * LDQ + (lh << 3)) * 2;
    const uint32_t aQl = aQh + (QL_OFF - QH_OFF);
    const uint32_t bKh = sb + KH_OFF + (uint32_t)(lm * LDK + n0 + (lh << 3)) * 2;
    const uint32_t bKl = bKh + (KL_OFF - KH_OFF);
    const uint32_t aPh = sb + PH_OFF + (uint32_t)((m0 + lm) * LDK + (lh << 3)) * 2;
    const uint32_t aPl = aPh + (PL_OFF - PH_OFF);
    const uint32_t bVh = sb + VH_OFF + (uint32_t)(lm * LDQ + (ng << 6) + (lh << 3)) * 2;
    const uint32_t bVl = bVh + (VL_OFF - VH_OFF);
    const uint32_t KSTEP_K = 16 * LDK * 2;       // 2304
    const uint32_t KSTEP_V = 16 * LDQ * 2;       // 4352

    const int tb = (ch * NT) / NCH, te = ((ch + 1) * NT) / NCH;
    const float* kbase = ktc + (size_t)kv * HD * CACHE;
    const float* vbase = vc  + (size_t)kv * CACHE * HD;

    for (int t = tb; t < te; t++) {
        const int c0 = t * TC;
        __syncthreads();   // prev tile's GEMMs done with K/P/V

        // ---- load + split K tile: [k=d 128][c 64], pitch LDK ----
        #pragma unroll
        for (int r = 0; r < 8; r++) {
            int i4 = tid + r * NTHR;             // 0..2047
            int k = i4 >> 4, c4 = (i4 & 15) << 2;
            int c = c0 + c4;
            float4 v = (c < CACHE) ? *(const float4*)(kbase + (size_t)k * CACHE + c)
                                   : make_float4(0.f, 0.f, 0.f, 0.f);
            uint32_t h0, l0, h1, l1;
            split_pack(v.x, v.y, h0, l0); split_pack(v.z, v.w, h1, l1);
            int bo = (k * LDK + c4) * 2;
            *(uint2*)(smc + KH_OFF + bo) = make_uint2(h0, h1);
            *(uint2*)(smc + KL_OFF + bo) = make_uint2(l0, l1);
        }
        // ---- load + split V tile: [c 64][d 128], pitch LDQ ----
        #pragma unroll
        for (int r = 0; r < 8; r++) {
            int i4 = tid + r * NTHR;
            int cl = i4 >> 5, d4 = (i4 & 31) << 2;
            int c = c0 + cl;
            float4 v = (c < CACHE) ? *(const float4*)(vbase + (size_t)c * HD + d4)
                                   : make_float4(0.f, 0.f, 0.f, 0.f);
            uint32_t h0, l0, h1, l1;
            split_pack(v.x, v.y, h0, l0); split_pack(v.z, v.w, h1, l1);
            int bo = (cl * LDQ + d4) * 2;
            *(uint2*)(smc + VH_OFF + bo) = make_uint2(h0, h1);
            *(uint2*)(smc + VL_OFF + bo) = make_uint2(l0, l1);
        }
        // ---- last tile: scale new K/V inline, overlay, and emit sk/sv outputs ----
        if (t == NT - 1) {
            int cl0 = CACHE - c0;                // 32
            float s = kqs[0];
            for (int i = tid; i < BATCH * HD; i += NTHR) {
                int b = i >> 7, d = i & 127;
                float kvv = keys[kv * BATCH * HD + i] * s;
                float vvv = fmaxf(values[kv * BATCH * HD + i], -10000.0f);
                out_sk[kv * BATCH * HD + i] = kvv;
                out_sv[kv * BATCH * HD + i] = vvv;
                __nv_bfloat16 h, l;
                split1(kvv, h, l);
                *(__nv_bfloat16*)(smc + KH_OFF + (d * LDK + cl0 + b) * 2) = h;
                *(__nv_bfloat16*)(smc + KL_OFF + (d * LDK + cl0 + b) * 2) = l;
                split1(vvv, h, l);
                *(__nv_bfloat16*)(smc + VH_OFF + ((cl0 + b) * LDQ + d) * 2) = h;
                *(__nv_bfloat16*)(smc + VL_OFF + ((cl0 + b) * LDQ + d) * 2) = l;
            }
        }
        __syncthreads();

        // ---- GEMM1: S[64, 64] = Q * K^T (3-pass split) ----
        float accS[4][4];
        #pragma unroll
        for (int j = 0; j < 4; j++)
            #pragma unroll
            for (int i = 0; i < 4; i++) accS[j][i] = 0.0f;
        {
            uint32_t aa = aQh, bh = bKh, bl = bKl;
            #pragma unroll
            for (int kk = 0; kk < 8; kk++) {
                uint32_t a[4], b0[4], b1[4], e0[4], e1[4];
                ldsm4(a, aa);
                ldsm4t(b0, bh); ldsm4t(b1, bh + 32);
                ldsm4t(e0, bl); ldsm4t(e1, bl + 32);
                mma16816(accS[0], a, b0[0], b0[1]); mma16816(accS[1], a, b0[2], b0[3]);
                mma16816(accS[2], a, b1[0], b1[1]); mma16816(accS[3], a, b1[2], b1[3]);
                mma16816(accS[0], a, e0[0], e0[1]); mma16816(accS[1], a, e0[2], e0[3]);
                mma16816(accS[2], a, e1[0], e1[1]); mma16816(accS[3], a, e1[2], e1[3]);
                aa += 32; bh += KSTEP_K; bl += KSTEP_K;
            }
            aa = aQl; bh = bKh;
            #pragma unroll
            for (int kk = 0; kk < 8; kk++) {
                uint32_t a[4], b0[4], b1[4];
                ldsm4(a, aa);
                ldsm4t(b0, bh); ldsm4t(b1, bh + 32);
                mma16816(accS[0], a, b0[0], b0[1]); mma16816(accS[1], a, b0[2], b0[3]);
                mma16816(accS[2], a, b1[0], b1[1]); mma16816(accS[3], a, b1[2], b1[3]);
                aa += 32; bh += KSTEP_K;
            }
        }

        // ---- bias on last tile only ----
        if (t == NT - 1) {
            #pragma unroll
            for (int j = 0; j < 4; j++) {
                int cg = c0 + n0 + 8 * j + 2 * qt;
                const float* bp0 = bias + (size_t)(r0 & 15) * CTX + cg;
                const float* bp1 = bias + (size_t)(r1 & 15) * CTX + cg;
                accS[j][0] += bp0[0]; accS[j][1] += bp0[1];
                accS[j][2] += bp1[0]; accS[j][3] += bp1[1];
            }
        }

        // ---- online softmax (cross-warp over 2 n-groups) ----
        float mx0 = neg_inf(), mx1 = neg_inf();
        #pragma unroll
        for (int j = 0; j < 4; j++) {
            mx0 = fmaxf(mx0, fmaxf(accS[j][0], accS[j][1]));
            mx1 = fmaxf(mx1, fmaxf(accS[j][2], accS[j][3]));
        }
        mx0 = fmaxf(mx0, __shfl_xor_sync(0xffffffffu, mx0, 1));
        mx0 = fmaxf(mx0, __shfl_xor_sync(0xffffffffu, mx0, 2));
        mx1 = fmaxf(mx1, __shfl_xor_sync(0xffffffffu, mx1, 1));
        mx1 = fmaxf(mx1, __shfl_xor_sync(0xffffffffu, mx1, 2));
        if (qt == 0) { red_max[ng * 64 + r0] = mx0; red_max[ng * 64 + r1] = mx1; }
        __syncthreads();

        float mt0 = fmaxf(red_max[r0], red_max[64 + r0]);
        float mt1 = fmaxf(red_max[r1], red_max[64 + r1]);
        float mold0 = m_s[r0], mold1 = m_s[r1];
        float mnew0 = fmaxf(mold0, mt0), mnew1 = fmaxf(mold1, mt1);
        float scl0 = __expf(mold0 - mnew0), scl1 = __expf(mold1 - mnew1);

        float sum0 = 0.f, sum1 = 0.f;
        #pragma unroll
        for (int j = 0; j < 4; j++) {
            float p00 = __expf(accS[j][0] - mnew0);
            float p01 = __expf(accS[j][1] - mnew0);
            float p10 = __expf(accS[j][2] - mnew1);
            float p11 = __expf(accS[j][3] - mnew1);
            sum0 += p00 + p01; sum1 += p10 + p11;
            uint32_t h, l;
            int bo0 = (r0 * LDK + n0 + 8 * j + 2 * qt) * 2;
            split_pack(p00, p01, h, l);
            *(uint32_t*)(smc + PH_OFF + bo0) = h;
            *(uint32_t*)(smc + PL_OFF + bo0) = l;
            int bo1 = (r1 * LDK + n0 + 8 * j + 2 * qt) * 2;
            split_pack(p10, p11, h, l);
            *(uint32_t*)(smc + PH_OFF + bo1) = h;
            *(uint32_t*)(smc + PL_OFF + bo1) = l;
        }
        sum0 += __shfl_xor_sync(0xffffffffu, sum0, 1);
        sum0 += __shfl_xor_sync(0xffffffffu, sum0, 2);
        sum1 += __shfl_xor_sync(0xffffffffu, sum1, 1);
        sum1 += __shfl_xor_sync(0xffffffffu, sum1, 2);
        if (qt == 0) { red_sum[ng * 64 + r0] = sum0; red_sum[ng * 64 + r1] = sum1; }
        __syncthreads();

        if (ng == 0 && qt == 0) {   // one owner per row updates running stats
            float s0 = red_sum[r0] + red_sum[64 + r0];
            float s1 = red_sum[r1] + red_sum[64 + r1];
            l_s[r0] = l_s[r0] * scl0 + s0;  m_s[r0] = mnew0;
            l_s[r1] = l_s[r1] * scl1 + s1;  m_s[r1] = mnew1;
        }

        // ---- rescale accO, GEMM2: O[64,128] += P * V (3-pass split) ----
        #pragma unroll
        for (int j = 0; j < 8; j++) {
            accO[j][0] *= scl0; accO[j][1] *= scl0;
            accO[j][2] *= scl1; accO[j][3] *= scl1;
        }
        {
            uint32_t aa = aPh, bh = bVh, bl = bVl;
            #pragma unroll
            for (int kk = 0; kk < 4; kk++) {
                uint32_t a[4], b0[4], b1[4], b2[4], b3[4];
                ldsm4(a, aa);
                ldsm4t(b0, bh); ldsm4t(b1, bh + 32);
                ldsm4t(b2, bh + 64); ldsm4t(b3, bh + 96);
                mma16816(accO[0], a, b0[0], b0[1]); mma16816(accO[1], a, b0[2], b0[3]);
                mma16816(accO[2], a, b1[0], b1[1]); mma16816(accO[3], a, b1[2], b1[3]);
                mma16816(accO[4], a, b2[0], b2[1]); mma16816(accO[5], a, b2[2], b2[3]);
                mma16816(accO[6], a, b3[0], b3[1]); mma16816(accO[7], a, b3[2], b3[3]);
                ldsm4t(b0, bl); ldsm4t(b1, bl + 32);
                ldsm4t(b2, bl + 64); ldsm4t(b3, bl + 96);
                mma16816(accO[0], a, b0[0], b0[1]); mma16816(accO[1], a, b0[2], b0[3]);
                mma16816(accO[2], a, b1[0], b1[1]); mma16816(accO[3], a, b1[2], b1[3]);
                mma16816(accO[4], a, b2[0], b2[1]); mma16816(accO[5], a, b2[2], b2[3]);
                mma16816(accO[6], a, b3[0], b3[1]); mma16816(accO[7], a, b3[2], b3[3]);
                aa += 32; bh += KSTEP_V; bl += KSTEP_V;
            }
            aa = aPl; bh = bVh;
            #pragma unroll
            for (int kk = 0; kk < 4; kk++) {
                uint32_t a[4], b0[4], b1[4], b2[4], b3[4];
                ldsm4(a, aa);
                ldsm4t(b0, bh); ldsm4t(b1, bh + 32);
                ldsm4t(b2, bh + 64); ldsm4t(b3, bh + 96);
                mma16816(accO[0], a, b0[0], b0[1]); mma16816(accO[1], a, b0[2], b0[3]);
                mma16816(accO[2], a, b1[0], b1[1]); mma16816(accO[3], a, b1[2], b1[3]);
                mma16816(accO[4], a, b2[0], b2[1]); mma16816(accO[5], a, b2[2], b2[3]);
                mma16816(accO[6], a, b3[0], b3[1]); mma16816(accO[7], a, b3[2], b3[3]);
                aa += 32; bh += KSTEP_V;
            }
        }
    }

    // ---- write partials ----
    __syncthreads();
    const int pbase = (ch * KV + kv) * NQ;
    if (tid < NQ) { g_pm[pbase + tid] = m_s[tid]; g_pl[pbase + tid] = l_s[tid]; }
    #pragma unroll
    for (int j = 0; j < 8; j++) {
        int d = (ng << 6) + 8 * j + 2 * qt;
        *(float2*)&g_pout[(size_t)(pbase + r0) * HD + d] = make_float2(accO[j][0], accO[j][1]);
        *(float2*)&g_pout[(size_t)(pbase + r1) * HD + d] = make_float2(accO[j][2], accO[j][3]);
    }
}

// -------- kernel 2: logsumexp combine over chunks --------
__global__ void k_combine(float* __restrict__ out) {
    int row = blockIdx.x;        // kv*64 + q
    int d = threadIdx.x;         // 0..127
    __shared__ float ms[NCH], ls[NCH];
    if (d < NCH) {
        ms[d] = g_pm[d * (KV * NQ) + row];
        ls[d] = g_pl[d * (KV * NQ) + row];
    }
    __syncthreads();
    float mstar = neg_inf();
    #pragma unroll
    for (int c = 0; c < NCH; c++) mstar = fmaxf(mstar, ms[c]);
    float num = 0.f, den = 0.f;
    for (int c = 0; c < NCH; c++) {
        float w = __expf(ms[c] - mstar);
        den += w * ls[c];
        num += w * g_pout[((size_t)c * (KV * NQ) + row) * HD + d];
    }
    out[(size_t)row * HD + d] = num / den;
}

extern "C" void kernel_launch(void* const* d_in, const int* in_sizes, int n_in,
                              void* d_out, int out_size) {
    const float* queries = (const float*)d_in[0];
    const float* keys    = (const float*)d_in[1];
    const float* ktc     = (const float*)d_in[2];
    const float* values  = (const float*)d_in[3];
    const float* vcache  = (const float*)d_in[4];
    const float* bias    = (const float*)d_in[5];
    const float* kqs     = (const float*)d_in[6];
    float* out = (float*)d_out;
    float* out_sk = out + NH * BATCH * HD;            // 65536
    float* out_sv = out_sk + KV * BATCH * HD;         // 81920

    cudaFuncSetAttribute(k_attn, cudaFuncAttributeMaxDynamicSharedMemorySize, SMEM_BYTES);
    k_attn<<<dim3(NCH, KV), NTHR, SMEM_BYTES>>>(queries, ktc, vcache, bias,
                                                keys, values, kqs, out_sk, out_sv);

    k_combine<<<KV * NQ, HD>>>(out);
}